// round 8
// baseline (speedup 1.0000x reference)
#include <cuda_runtime.h>
#include <cstdint>

// Problem constants
#define NB 16      // batches
#define CH 256     // c*h rows
#define SD 3200    // contraction dim, ordered s' = n*128 + w
#define ELEM_PER_B 819200   // 16*25*16*128 floats per batch per tensor
#define NSPLIT 2   // split-K factor for GEMM1
#define KHALF 1600 // SD / NSPLIT
#define KC 32
#define AST 36
#define BST 36
#define B2ST 136

#define SMEM1 (2 * (64 * AST + 128 * BST) * 4)   // 55296 B
#define SMEM2 (2 * (64 * AST + KC * B2ST) * 4)   // 53248 B

// Scratch (static device globals only)
__device__ float g_att[NSPLIT][NB * CH * CH];  // partials; [0] holds softmax result
__device__ float g_invq[NB * CH];
__device__ float g_invk[NB * CH];

// ---------------------------------------------------------------------------
// cp.async helpers
// ---------------------------------------------------------------------------
__device__ __forceinline__ void cp16(uint32_t dst, const float* src) {
    asm volatile("cp.async.cg.shared.global [%0], [%1], 16;\n" :: "r"(dst), "l"(src));
}
__device__ __forceinline__ void cp_commit() {
    asm volatile("cp.async.commit_group;\n");
}
__device__ __forceinline__ void cp_wait0() {
    asm volatile("cp.async.wait_group 0;\n" ::: "memory");
}

// ---------------------------------------------------------------------------
// Row inverse norms over the 3200-dim for Q (y=0) and K (y=1).
// ---------------------------------------------------------------------------
__global__ void norm_kernel(const float4* __restrict__ q,
                            const float4* __restrict__ k) {
    int row = blockIdx.x;                  // b*256 + t
    int t = row & 255, b = row >> 8;
    const float4* src = (blockIdx.y == 0 ? q : k)
        + (size_t)b * 204800 + (size_t)(t >> 4) * 12800 + (size_t)(t & 15) * 32;
    float sum = 0.f;
    for (int i = threadIdx.x; i < 800; i += 256) {
        int n = i >> 5, w4 = i & 31;
        float4 vv = src[n * 512 + w4];
        sum += vv.x * vv.x + vv.y * vv.y + vv.z * vv.z + vv.w * vv.w;
    }
    __shared__ float red[32];
    #pragma unroll
    for (int o = 16; o > 0; o >>= 1) sum += __shfl_xor_sync(~0u, sum, o);
    if ((threadIdx.x & 31) == 0) red[threadIdx.x >> 5] = sum;
    __syncthreads();
    if (threadIdx.x < 32) {
        float s2 = (threadIdx.x < 8) ? red[threadIdx.x] : 0.f;
        #pragma unroll
        for (int o = 4; o > 0; o >>= 1) s2 += __shfl_xor_sync(~0u, s2, o);
        if (threadIdx.x == 0) {
            float inv = 1.f / fmaxf(sqrtf(s2), 1e-12f);
            (blockIdx.y == 0 ? g_invq : g_invk)[row] = inv;
        }
    }
}

// ---------------------------------------------------------------------------
// tf32 mma.sync helper: D += A(16x8) * B(8x8)
// ---------------------------------------------------------------------------
__device__ __forceinline__ void mma_tf32(float* c, const uint32_t* a, const uint32_t* b) {
    asm volatile(
        "mma.sync.aligned.m16n8k8.row.col.f32.tf32.tf32.f32 "
        "{%0,%1,%2,%3}, {%4,%5,%6,%7}, {%8,%9}, {%0,%1,%2,%3};\n"
        : "+f"(c[0]), "+f"(c[1]), "+f"(c[2]), "+f"(c[3])
        : "r"(a[0]), "r"(a[1]), "r"(a[2]), "r"(a[3]), "r"(b[0]), "r"(b[1]));
}

// ---------------------------------------------------------------------------
// GEMM1 (split-K x2, cp.async 2-stage): att_part[half] = partial Q.K^T
// CTA tile 64x128, K-chunk 32, 4 warps. Grid: (16, 16).
// One __syncthreads per chunk: wait0 -> barrier -> issue next -> compute.
// ---------------------------------------------------------------------------
#define G1_ISSUE(buf, ci) do {                                                 \
    int ks_ = ks0 + (ci) * KC;                                                 \
    int soff_ = (ks_ >> 7) * 2048 + (ks_ & 127) + c4 * 4;                      \
    _Pragma("unroll")                                                          \
    for (int p = 0; p < 4; p++)                                                \
        cp16(as_u32 + (((buf) * 64 * AST + (p * 16 + rowA) * AST + c4 * 4) << 2), \
             Ab + (size_t)(t0 / 16 + p) * 51200 + rowA * 128 + soff_);         \
    _Pragma("unroll")                                                          \
    for (int p = 0; p < 8; p++)                                                \
        cp16(bs_u32 + (((buf) * 128 * BST + (p * 16 + rowA) * BST + c4 * 4) << 2), \
             Bb + (size_t)(r0 / 16 + p) * 51200 + rowA * 128 + soff_);         \
} while (0)

__global__ __launch_bounds__(128, 4) void gemm1_kernel(const float* __restrict__ q,
                                                       const float* __restrict__ k) {
    extern __shared__ float sm1[];
    float* Asm = sm1;                    // [2][64*AST]
    float* Bsm = sm1 + 2 * 64 * AST;     // [2][128*BST]
    uint32_t as_u32 = (uint32_t)__cvta_generic_to_shared(Asm);
    uint32_t bs_u32 = (uint32_t)__cvta_generic_to_shared(Bsm);

    int b    = blockIdx.y;
    int half = blockIdx.x >> 3;
    int tm   = (blockIdx.x >> 1) & 3;
    int tn   = blockIdx.x & 1;
    int t0 = tm * 64;
    int r0 = tn * 128;

    int tid  = threadIdx.x;
    int warp = tid >> 5, lane = tid & 31;
    int wm = warp >> 1, wn = warp & 1;
    int gid = lane >> 2, tig = lane & 3;

    const float* Ab = q + (size_t)b * ELEM_PER_B;
    const float* Bb = k + (size_t)b * ELEM_PER_B;

    float acc[2][8][4];
    #pragma unroll
    for (int mi = 0; mi < 2; mi++)
        #pragma unroll
        for (int ni = 0; ni < 8; ni++)
            #pragma unroll
            for (int x = 0; x < 4; x++) acc[mi][ni][x] = 0.f;

    int rowA = tid >> 3;       // 0..15 = (t&15) of the loaded row
    int c4   = tid & 7;        // 16B column within 128B chunk

    const int ks0 = half * KHALF;
    const int nch = KHALF / KC;    // 50

    G1_ISSUE(0, 0);
    cp_commit();

    for (int i = 0; i < nch; i++) {
        cp_wait0();          // this thread's chunk-i copies done
        __syncthreads();     // all threads' copies done; prev compute finished
        if (i + 1 < nch) { G1_ISSUE((i + 1) & 1, i + 1); cp_commit(); }

        const float* As = Asm + (i & 1) * 64 * AST;
        const float* Bs = Bsm + (i & 1) * 128 * BST;

        #pragma unroll
        for (int kk = 0; kk < KC; kk += 8) {
            uint32_t af[2][4];
            #pragma unroll
            for (int mi = 0; mi < 2; mi++) {
                int rA = wm * 32 + mi * 16 + gid;
                af[mi][0] = __float_as_uint(As[rA * AST + kk + tig]);
                af[mi][1] = __float_as_uint(As[(rA + 8) * AST + kk + tig]);
                af[mi][2] = __float_as_uint(As[rA * AST + kk + tig + 4]);
                af[mi][3] = __float_as_uint(As[(rA + 8) * AST + kk + tig + 4]);
            }
            uint32_t bf[8][2];
            #pragma unroll
            for (int ni = 0; ni < 8; ni++) {
                int rB = wn * 64 + ni * 8 + gid;
                bf[ni][0] = __float_as_uint(Bs[rB * BST + kk + tig]);
                bf[ni][1] = __float_as_uint(Bs[rB * BST + kk + tig + 4]);
            }
            #pragma unroll
            for (int mi = 0; mi < 2; mi++)
                #pragma unroll
                for (int ni = 0; ni < 8; ni++)
                    mma_tf32(acc[mi][ni], af[mi], bf[ni]);
        }
    }

    float* Cg = g_att[half] + (size_t)b * 256 * 256;
    #pragma unroll
    for (int mi = 0; mi < 2; mi++) {
        int row = t0 + wm * 32 + mi * 16 + gid;
        #pragma unroll
        for (int ni = 0; ni < 8; ni++) {
            int col = r0 + wn * 64 + ni * 8 + tig * 2;
            *(float2*)(&Cg[row * 256 + col])       = make_float2(acc[mi][ni][0], acc[mi][ni][1]);
            *(float2*)(&Cg[(row + 8) * 256 + col]) = make_float2(acc[mi][ni][2], acc[mi][ni][3]);
        }
    }
}

// ---------------------------------------------------------------------------
// Softmax: combine split-K partials, scale, causal mask, softmax over r.
// ---------------------------------------------------------------------------
__global__ void softmax_kernel() {
    __shared__ float red[33];
    int bt = blockIdx.x;
    int t  = bt & 255;
    int b  = bt >> 8;
    int r  = threadIdx.x;
    size_t idx = (size_t)bt * 256 + r;

    float x = (g_att[0][idx] + g_att[1][idx]) * g_invq[bt] * g_invk[(b << 8) + r];
    if (r > t) x = -1e15f;

    float m = x;
    #pragma unroll
    for (int o = 16; o > 0; o >>= 1) m = fmaxf(m, __shfl_xor_sync(~0u, m, o));
    if ((r & 31) == 0) red[r >> 5] = m;
    __syncthreads();
    if (r < 32) {
        float m2 = (r < 8) ? red[r] : -3.4e38f;
        #pragma unroll
        for (int o = 4; o > 0; o >>= 1) m2 = fmaxf(m2, __shfl_xor_sync(~0u, m2, o));
        if (r == 0) red[32] = m2;
    }
    __syncthreads();
    float e = expf(x - red[32]);

    float s = e;
    #pragma unroll
    for (int o = 16; o > 0; o >>= 1) s += __shfl_xor_sync(~0u, s, o);
    if ((r & 31) == 0) red[r >> 5] = s;
    __syncthreads();
    if (r < 32) {
        float s2 = (r < 8) ? red[r] : 0.f;
        #pragma unroll
        for (int o = 4; o > 0; o >>= 1) s2 += __shfl_xor_sync(~0u, s2, o);
        if (r == 0) red[32] = s2;
    }
    __syncthreads();
    g_att[0][idx] = e / red[32];
}

// ---------------------------------------------------------------------------
// GEMM2 (cp.async 2-stage): out = att @ V' + V'. CTA tile 64x128, K=256.
// Grid: (100, 16).
// ---------------------------------------------------------------------------
#define G2_ISSUE(buf, ci) do {                                                 \
    int ks_ = (ci) * KC;                                                       \
    _Pragma("unroll")                                                          \
    for (int p = 0; p < 4; p++)                                                \
        cp16(as_u32 + (((buf) * 64 * AST + (p * 16 + rowA) * AST + c4a * 4) << 2), \
             Ag + (size_t)(p * 16 + rowA) * 256 + ks_ + c4a * 4);              \
    _Pragma("unroll")                                                          \
    for (int p = 0; p < 8; p++) {                                              \
        int r_ = ks_ + p * 4 + rowB;                                           \
        cp16(bs_u32 + (((buf) * KC * B2ST + (p * 4 + rowB) * B2ST + c4b * 4) << 2), \
             Vb + (size_t)(r_ >> 4) * 51200 + (r_ & 15) * 128 + c4b * 4);      \
    }                                                                          \
} while (0)

__global__ __launch_bounds__(128, 4) void gemm2_kernel(const float* __restrict__ v,
                                                       float* __restrict__ out) {
    extern __shared__ float sm2[];
    float* Asm = sm2;                    // [2][64*AST]
    float* Bsm = sm2 + 2 * 64 * AST;     // [2][KC*B2ST]
    uint32_t as_u32 = (uint32_t)__cvta_generic_to_shared(Asm);
    uint32_t bs_u32 = (uint32_t)__cvta_generic_to_shared(Bsm);

    int b  = blockIdx.y;
    int bx = blockIdx.x;
    int tm = bx / 25;
    int sn = bx % 25;
    int t0 = tm * 64;

    int tid  = threadIdx.x;
    int warp = tid >> 5, lane = tid & 31;
    int wm = warp >> 1, wn = warp & 1;
    int gid = lane >> 2, tig = lane & 3;

    const float* Ag = g_att[0] + (size_t)(b * 256 + t0) * 256;
    const float* Vb = v + (size_t)b * ELEM_PER_B + (size_t)sn * 2048;

    float acc[2][8][4];
    #pragma unroll
    for (int mi = 0; mi < 2; mi++)
        #pragma unroll
        for (int ni = 0; ni < 8; ni++)
            #pragma unroll
            for (int x = 0; x < 4; x++) acc[mi][ni][x] = 0.f;

    int rowA = tid >> 3;   // 0..15
    int c4a  = tid & 7;
    int rowB = tid >> 5;   // 0..3
    int c4b  = tid & 31;

    const int nch = 256 / KC;   // 8

    G2_ISSUE(0, 0);
    cp_commit();

    for (int i = 0; i < nch; i++) {
        cp_wait0();
        __syncthreads();
        if (i + 1 < nch) { G2_ISSUE((i + 1) & 1, i + 1); cp_commit(); }

        const float* As = Asm + (i & 1) * 64 * AST;
        const float* Bs = Bsm + (i & 1) * KC * B2ST;

        #pragma unroll
        for (int kk = 0; kk < KC; kk += 8) {
            uint32_t af[2][4];
            #pragma unroll
            for (int mi = 0; mi < 2; mi++) {
                int rA = wm * 32 + mi * 16 + gid;
                af[mi][0] = __float_as_uint(As[rA * AST + kk + tig]);
                af[mi][1] = __float_as_uint(As[(rA + 8) * AST + kk + tig]);
                af[mi][2] = __float_as_uint(As[rA * AST + kk + tig + 4]);
                af[mi][3] = __float_as_uint(As[(rA + 8) * AST + kk + tig + 4]);
            }
            uint32_t bf[8][2];
            #pragma unroll
            for (int ni = 0; ni < 8; ni++) {
                int cB = wn * 64 + ni * 8 + gid;
                bf[ni][0] = __float_as_uint(Bs[(kk + tig) * B2ST + cB]);
                bf[ni][1] = __float_as_uint(Bs[(kk + tig + 4) * B2ST + cB]);
            }
            #pragma unroll
            for (int mi = 0; mi < 2; mi++)
                #pragma unroll
                for (int ni = 0; ni < 8; ni++)
                    mma_tf32(acc[mi][ni], af[mi], bf[ni]);
        }
    }

    // epilogue: add V buffer (read at the OUTPUT address in v) and store
    #pragma unroll
    for (int mi = 0; mi < 2; mi++) {
        #pragma unroll
        for (int half = 0; half < 2; half++) {
            int t = t0 + wm * 32 + mi * 16 + gid + half * 8;
            size_t obase = (size_t)b * ELEM_PER_B + (size_t)(t >> 4) * 51200
                         + (size_t)sn * 2048 + (size_t)(t & 15) * 128;
            #pragma unroll
            for (int ni = 0; ni < 8; ni++) {
                int w = wn * 64 + ni * 8 + tig * 2;
                float2 vv = *(const float2*)(v + obase + w);
                float2 o;
                o.x = acc[mi][ni][half * 2 + 0] + vv.x;
                o.y = acc[mi][ni][half * 2 + 1] + vv.y;
                *(float2*)(out + obase + w) = o;
            }
        }
    }
}

// ---------------------------------------------------------------------------
// Launch
// ---------------------------------------------------------------------------
extern "C" void kernel_launch(void* const* d_in, const int* in_sizes, int n_in,
                              void* d_out, int out_size) {
    const float* q = (const float*)d_in[0];
    const float* k = (const float*)d_in[1];
    const float* v = (const float*)d_in[2];
    float* out = (float*)d_out;

    cudaFuncSetAttribute(gemm1_kernel, cudaFuncAttributeMaxDynamicSharedMemorySize, SMEM1);
    cudaFuncSetAttribute(gemm2_kernel, cudaFuncAttributeMaxDynamicSharedMemorySize, SMEM2);

    norm_kernel<<<dim3(4096, 2), 256>>>((const float4*)q, (const float4*)k);
    gemm1_kernel<<<dim3(16, NB), 128, SMEM1>>>(q, k);
    softmax_kernel<<<4096, 256>>>();
    gemm2_kernel<<<dim3(100, NB), 128, SMEM2>>>(v, out);
}